// round 6
// baseline (speedup 1.0000x reference)
#include <cuda_runtime.h>

#define HIDDEN 128
#define NTYPES 28
#define MAX_CYCLES 500000

// Packed per-cycle type histogram: 2 x u64, 14 types per word, 4-bit fields.
// Zero-initialized at module load; k_final re-zeroes after reading (self-clean),
// so every kernel_launch/replay sees it zeroed. Integer red-adds => deterministic.
__device__ ulonglong2 g_hist[MAX_CYCLES];   // 8 MB, L2-resident

// ---------------------------------------------------------------------------
// Scatter: one red.global.add.u64 per incidence. No return value, no cursor,
// no type-byte store.
// ---------------------------------------------------------------------------
__global__ void __launch_bounds__(256)
k_scatter(const int* __restrict__ x,
          const int* __restrict__ atom_row,
          const int* __restrict__ cyc_row, int n)
{
    const int n4 = n >> 2;
    int i = blockIdx.x * blockDim.x + threadIdx.x;
    const int stride = gridDim.x * blockDim.x;
    const int4* a4 = reinterpret_cast<const int4*>(atom_row);
    const int4* c4 = reinterpret_cast<const int4*>(cyc_row);

    for (; i < n4; i += stride) {
        int4 a = __ldg(&a4[i]);
        int4 c = __ldg(&c4[i]);
        int atoms[4] = {a.x, a.y, a.z, a.w};
        int cycs[4]  = {c.x, c.y, c.z, c.w};
#pragma unroll
        for (int k = 0; k < 4; k++) {
            int t = __ldg(&x[atoms[k]]);
            int w = (t >= 14) ? 1 : 0;
            int f = t - 14 * w;
            unsigned long long inc = 1ULL << (f * 4);
            unsigned long long* dst =
                reinterpret_cast<unsigned long long*>(&g_hist[cycs[k]]) + w;
            asm volatile("red.global.add.u64 [%0], %1;"
                         :: "l"(dst), "l"(inc) : "memory");
        }
    }
    // tail (n % 4 != 0)
    for (int j = (n4 << 2) + blockIdx.x * blockDim.x + threadIdx.x; j < n;
         j += stride) {
        int t = __ldg(&x[__ldg(&atom_row[j])]);
        int cyc = __ldg(&cyc_row[j]);
        int w = (t >= 14) ? 1 : 0;
        int f = t - 14 * w;
        unsigned long long inc = 1ULL << (f * 4);
        unsigned long long* dst =
            reinterpret_cast<unsigned long long*>(&g_hist[cyc]) + w;
        asm volatile("red.global.add.u64 [%0], %1;"
                     :: "l"(dst), "l"(inc) : "memory");
    }
}

// ---------------------------------------------------------------------------
// Final: one warp per cycle. Decode packed hist (nonzero nibbles only),
// acc = sum cnt * emb_row from smem, one coalesced 512 B store, then
// self-clean the hist entry. ILP-2 across two cycles per iteration.
// ---------------------------------------------------------------------------
__device__ __forceinline__ void ld_hist_v2(const ulonglong2* p,
                                           unsigned long long& lo,
                                           unsigned long long& hi)
{
    asm volatile("ld.global.v2.u64 {%0, %1}, [%2];"
                 : "=l"(lo), "=l"(hi) : "l"(p));
}

__device__ __forceinline__ void decode_word(unsigned long long w, int tbase,
                                            int lane, const float4* s_emb,
                                            float4& acc)
{
    while (w) {
        int b = __ffsll(w) - 1;
        int f = b >> 2;
        float cnt = (float)((w >> (f * 4)) & 0xFULL);
        w &= ~(0xFULL << (f * 4));
        float4 v = s_emb[(tbase + f) * 32 + lane];
        acc.x += cnt * v.x; acc.y += cnt * v.y;
        acc.z += cnt * v.z; acc.w += cnt * v.w;
    }
}

__global__ void __launch_bounds__(256)
k_final(const float* __restrict__ emb, float* __restrict__ out, int ncyc)
{
    __shared__ float4 s_emb[NTYPES * 32];
    for (int i = threadIdx.x; i < NTYPES * 32; i += blockDim.x)
        s_emb[i] = reinterpret_cast<const float4*>(emb)[i];
    __syncthreads();

    const int lane = threadIdx.x & 31;
    const int warp = (blockIdx.x * blockDim.x + threadIdx.x) >> 5;
    const int nw   = (gridDim.x * blockDim.x) >> 5;
    float4* out4 = reinterpret_cast<float4*>(out);
    const ulonglong2 zero2 = make_ulonglong2(0ULL, 0ULL);

    for (int c = warp; c < ncyc; c += 2 * nw) {
        const int c2 = c + nw;
        // Issue both broadcast hist loads before any decode (MLP=2).
        unsigned long long h1x, h1y, h2x = 0ULL, h2y = 0ULL;
        ld_hist_v2(&g_hist[c], h1x, h1y);
        if (c2 < ncyc) ld_hist_v2(&g_hist[c2], h2x, h2y);

        float4 acc1 = make_float4(0.f, 0.f, 0.f, 0.f);
        decode_word(h1x, 0,  lane, s_emb, acc1);
        decode_word(h1y, 14, lane, s_emb, acc1);
        out4[(size_t)c * 32 + lane] = acc1;

        if (c2 < ncyc) {
            float4 acc2 = make_float4(0.f, 0.f, 0.f, 0.f);
            decode_word(h2x, 0,  lane, s_emb, acc2);
            decode_word(h2y, 14, lane, s_emb, acc2);
            out4[(size_t)c2 * 32 + lane] = acc2;
        }

        // Self-clean for the next launch/replay (one lane per entry).
        if (lane == 0) {
            g_hist[c] = zero2;
            if (c2 < ncyc) g_hist[c2] = zero2;
        }
    }
}

// ---------------------------------------------------------------------------
// Inputs (metadata order):
//   d_in[0]: x             int32 [500000]
//   d_in[1]: atom_to_cycle int32 [2, 2000000]  (row 0 = atom idx, row 1 = cycle idx)
//   d_in[2]: emb_weight    fp32  [28, 128]
// Output: fp32 [500000, 128]
// ---------------------------------------------------------------------------
extern "C" void kernel_launch(void* const* d_in, const int* in_sizes, int n_in,
                              void* d_out, int out_size)
{
    const int*   x   = (const int*)d_in[0];
    const int*   a2c = (const int*)d_in[1];
    const float* emb = (const float*)d_in[2];
    float*       out = (float*)d_out;

    const int n_inc = in_sizes[1] / 2;
    const int ncyc  = out_size / HIDDEN;

    k_scatter<<<1184, 256>>>(x, a2c, a2c + n_inc, n_inc);
    k_final<<<4736, 256>>>(emb, out, ncyc);
}

// round 7
// speedup vs baseline: 1.5683x; 1.5683x over previous
#include <cuda_runtime.h>

#define HIDDEN 128
#define NTYPES 28
#define MAX_CYCLES 500000

// Packed per-cycle type histogram: 2 x u64, 14 types/word, 4-bit fields.
// Zero at module load; k_final self-cleans after reading, so every replay
// sees zeros. Integer red-adds => deterministic.
__device__ ulonglong2 g_hist[MAX_CYCLES];   // 8 MB, L2-resident

// ---------------------------------------------------------------------------
// Scatter: one red.global.add.u64 per incidence (no return, no cursor).
// ---------------------------------------------------------------------------
__global__ void __launch_bounds__(256)
k_scatter(const int* __restrict__ x,
          const int* __restrict__ atom_row,
          const int* __restrict__ cyc_row, int n)
{
    const int n4 = n >> 2;
    int i = blockIdx.x * blockDim.x + threadIdx.x;
    const int stride = gridDim.x * blockDim.x;
    const int4* a4 = reinterpret_cast<const int4*>(atom_row);
    const int4* c4 = reinterpret_cast<const int4*>(cyc_row);

    for (; i < n4; i += stride) {
        int4 a = __ldg(&a4[i]);
        int4 c = __ldg(&c4[i]);
        int atoms[4] = {a.x, a.y, a.z, a.w};
        int cycs[4]  = {c.x, c.y, c.z, c.w};
#pragma unroll
        for (int k = 0; k < 4; k++) {
            int t = __ldg(&x[atoms[k]]);
            int w = (t >= 14) ? 1 : 0;
            int f = t - 14 * w;
            unsigned long long inc = 1ULL << (f * 4);
            unsigned long long* dst =
                reinterpret_cast<unsigned long long*>(&g_hist[cycs[k]]) + w;
            asm volatile("red.global.add.u64 [%0], %1;"
                         :: "l"(dst), "l"(inc) : "memory");
        }
    }
    for (int j = (n4 << 2) + blockIdx.x * blockDim.x + threadIdx.x; j < n;
         j += stride) {
        int t = __ldg(&x[__ldg(&atom_row[j])]);
        int cyc = __ldg(&cyc_row[j]);
        int w = (t >= 14) ? 1 : 0;
        int f = t - 14 * w;
        unsigned long long inc = 1ULL << (f * 4);
        unsigned long long* dst =
            reinterpret_cast<unsigned long long*>(&g_hist[cyc]) + w;
        asm volatile("red.global.add.u64 [%0], %1;"
                     :: "l"(dst), "l"(inc) : "memory");
    }
}

// ---------------------------------------------------------------------------
// Final: one warp per cycle (ILP-2). Lane l extracts count of type l from
// the uint4 view of the hist (32-bit ops, parallel across lanes); ballot of
// nonzero lanes gives a sparse 32-bit mask; loop its ~3.7 set bits with
// 32-bit ffs + shfl + smem FMA. One coalesced 512 B store per cycle.
// ---------------------------------------------------------------------------
__device__ __forceinline__ float extract_cnt(uint4 h, int lane)
{
    // types 0-7 -> h.x, 8-13 -> h.y, 14-21 -> h.z, 22-27 -> h.w
    unsigned w;
    int idx;
    if (lane < 14) { w = (lane < 8) ? h.x : h.y; idx = (lane < 8) ? lane : lane - 8; }
    else           { int m = lane - 14;
                     w = (m < 8) ? h.z : h.w;    idx = (m < 8) ? m : m - 8; }
    unsigned cnt = (w >> (idx * 4)) & 0xFu;
    if (lane >= NTYPES) cnt = 0;
    return (float)cnt;
}

__device__ __forceinline__ void accum_cycle(uint4 h, int lane,
                                            const float4* s_emb, float4& acc)
{
    float fcnt = extract_cnt(h, lane);
    unsigned mask = __ballot_sync(0xFFFFFFFFu, fcnt != 0.f);
    while (mask) {
        int t = __ffs(mask) - 1;
        mask &= mask - 1;
        float fc = __shfl_sync(0xFFFFFFFFu, fcnt, t);
        float4 v = s_emb[t * 32 + lane];
        acc.x += fc * v.x; acc.y += fc * v.y;
        acc.z += fc * v.z; acc.w += fc * v.w;
    }
}

__global__ void __launch_bounds__(256)
k_final(const float* __restrict__ emb, float* __restrict__ out, int ncyc)
{
    __shared__ float4 s_emb[NTYPES * 32];
    for (int i = threadIdx.x; i < NTYPES * 32; i += blockDim.x)
        s_emb[i] = reinterpret_cast<const float4*>(emb)[i];
    __syncthreads();

    const int lane = threadIdx.x & 31;
    const int warp = (blockIdx.x * blockDim.x + threadIdx.x) >> 5;
    const int nw   = (gridDim.x * blockDim.x) >> 5;
    float4* out4 = reinterpret_cast<float4*>(out);
    const uint4* hist4 = reinterpret_cast<const uint4*>(g_hist);
    const ulonglong2 zero2 = make_ulonglong2(0ULL, 0ULL);

    for (int c = warp; c < ncyc; c += 2 * nw) {
        const int c2 = c + nw;
        // Issue both broadcast hist loads up front (MLP=2).
        uint4 h1 = __ldg(&hist4[c]);
        uint4 h2 = (c2 < ncyc) ? __ldg(&hist4[c2]) : make_uint4(0, 0, 0, 0);

        float4 acc1 = make_float4(0.f, 0.f, 0.f, 0.f);
        accum_cycle(h1, lane, s_emb, acc1);
        out4[(size_t)c * 32 + lane] = acc1;

        if (c2 < ncyc) {
            float4 acc2 = make_float4(0.f, 0.f, 0.f, 0.f);
            accum_cycle(h2, lane, s_emb, acc2);
            out4[(size_t)c2 * 32 + lane] = acc2;
        }

        // Self-clean for the next launch/replay.
        if (lane == 0) {
            g_hist[c] = zero2;
            if (c2 < ncyc) g_hist[c2] = zero2;
        }
    }
}

// ---------------------------------------------------------------------------
// Inputs (metadata order):
//   d_in[0]: x             int32 [500000]
//   d_in[1]: atom_to_cycle int32 [2, 2000000]  (row 0 = atom idx, row 1 = cycle idx)
//   d_in[2]: emb_weight    fp32  [28, 128]
// Output: fp32 [500000, 128]
// ---------------------------------------------------------------------------
extern "C" void kernel_launch(void* const* d_in, const int* in_sizes, int n_in,
                              void* d_out, int out_size)
{
    const int*   x   = (const int*)d_in[0];
    const int*   a2c = (const int*)d_in[1];
    const float* emb = (const float*)d_in[2];
    float*       out = (float*)d_out;

    const int n_inc = in_sizes[1] / 2;
    const int ncyc  = out_size / HIDDEN;

    k_scatter<<<1184, 256>>>(x, a2c, a2c + n_inc, n_inc);
    k_final<<<4736, 256>>>(emb, out, ncyc);
}